// round 15
// baseline (speedup 1.0000x reference)
#include <cuda_runtime.h>
#include <cuda_fp16.h>
#include <math.h>

#define Bb 32
#define NS 4096
#define Dd 256
#define Hh 4
#define Ll 6
#define NQ 512
#define NK 1024
#define DH 64
#define ATTN_SCALE 0.125f

// ---------------- scratch (static device globals; no allocation) -------------
__device__ float  g_upd[Bb * NS * Dd];
__device__ float  g_hb [Bb * NQ * Dd];
__device__ float  g_t1f[Bb * NQ * Dd];
__device__ float  g_t2 [Bb * NQ * Dd];
__device__ __half g_qh [Bb * NQ * Dd];
__device__ __half g_kh [Bb * NK * Dd];
__device__ __half g_Qh [Bb * NQ * Dd];
__device__ __half g_Kh [Bb * NK * Dd];
__device__ __half g_Vh [Bb * NK * Dd];
__device__ __half g_ctxh[Bb * NQ * Dd];
__device__ __half g_hh [Bb * NQ * Dd];
__device__ __half g_t1h[Bb * NQ * Dd];
__device__ __half g_WT [6 * Dd * Dd];                  // transposed half weights [n][k]
__device__ unsigned long long g_mpk[Ll * NQ * 16];     // bit-packed masks

// ---------------- helpers ----------------------------------------------------
__device__ __forceinline__ float gelu_tanh(float x) {
    float x3 = x * x * x;
    return 0.5f * x * (1.f + tanhf(0.7978845608028654f * (x + 0.044715f * x3)));
}

__device__ __forceinline__ unsigned h2u(__half2 h) {
    return *reinterpret_cast<unsigned*>(&h);
}

__device__ __forceinline__ void mma_f16(float c[4], unsigned a0, unsigned a1,
                                        unsigned a2, unsigned a3,
                                        unsigned b0, unsigned b1) {
    asm volatile(
        "mma.sync.aligned.m16n8k16.row.col.f32.f16.f16.f32 "
        "{%0,%1,%2,%3}, {%4,%5,%6,%7}, {%8,%9}, {%0,%1,%2,%3};"
        : "+f"(c[0]), "+f"(c[1]), "+f"(c[2]), "+f"(c[3])
        : "r"(a0), "r"(a1), "r"(a2), "r"(a3), "r"(b0), "r"(b1));
}

__device__ __forceinline__ void cp_async16(__half* smem, const __half* gmem) {
    unsigned s = (unsigned)__cvta_generic_to_shared(smem);
    asm volatile("cp.async.cg.shared.global [%0], [%1], 16;" :: "r"(s), "l"(gmem));
}
#define CP_COMMIT() asm volatile("cp.async.commit_group;")
#define CP_WAIT0()  asm volatile("cp.async.wait_group 0;")

// two-value (sum, sumsq) 64-thread-group reduction; one sync round
__device__ __forceinline__ float2 gsum64x2(float a, float b, float2* part,
                                           int warp, int lane, int grp) {
#pragma unroll
    for (int o = 16; o; o >>= 1) {
        a += __shfl_xor_sync(0xffffffffu, a, o);
        b += __shfl_xor_sync(0xffffffffu, b, o);
    }
    if (lane == 0) part[warp] = make_float2(a, b);
    __syncthreads();
    float2 r0 = part[2 * grp], r1 = part[2 * grp + 1];
    return make_float2(r0.x + r1.x, r0.y + r1.y);
}

// ---------------- init: upd = copy(src) ---------------------------------------
__global__ void k_init(const float* __restrict__ src, float* __restrict__ upd, int n) {
    for (int i = blockIdx.x * blockDim.x + threadIdx.x; i < n; i += gridDim.x * blockDim.x)
        upd[i] = src[i];
}

// ---------------- final: out = upd - upd_in -----------------------------------
__global__ void k_final(const float* __restrict__ upd, const float* __restrict__ src,
                        float* __restrict__ out, int n) {
    for (int i = blockIdx.x * blockDim.x + threadIdx.x; i < n; i += gridDim.x * blockDim.x)
        out[i] = upd[i] - src[i];
}

// ---------------- pack masks into bits: mp[l][q][kt] --------------------------
__global__ void k_maskpack(const float* __restrict__ mask, unsigned long long* __restrict__ mp) {
    int w = blockIdx.x * blockDim.x + threadIdx.x;
    if (w >= Ll * NQ * 16) return;
    int kt = w & 15, q = (w >> 4) & (NQ - 1), l = w >> 13;
    const float* src = mask + ((size_t)l * NQ + q) * NK + kt * 64;
    unsigned long long bits = 0;
#pragma unroll
    for (int c = 0; c < 64; c += 4) {
        float4 v = *(const float4*)&src[c];
        bits |= ((unsigned long long)(v.x > 0.5f)) << c;
        bits |= ((unsigned long long)(v.y > 0.5f)) << (c + 1);
        bits |= ((unsigned long long)(v.z > 0.5f)) << (c + 2);
        bits |= ((unsigned long long)(v.w > 0.5f)) << (c + 3);
    }
    mp[w] = bits;
}

// ---------------- weight transpose + fp16 convert (once per launch) -----------
__global__ void k_prep(const float* __restrict__ Wq, const float* __restrict__ Wk,
                       const float* __restrict__ Wv, const float* __restrict__ Wo,
                       const float* __restrict__ W1, const float* __restrict__ W2,
                       __half* __restrict__ WT) {
    __shared__ float tile[32][33];
    int w = blockIdx.z;
    const float* W = (w == 0) ? Wq : (w == 1) ? Wk : (w == 2) ? Wv
                   : (w == 3) ? Wo : (w == 4) ? W1 : W2;
    int k0 = blockIdx.x * 32, n0 = blockIdx.y * 32;
    int tx = threadIdx.x, ty = threadIdx.y;
#pragma unroll
    for (int r = 0; r < 32; r += 8)
        tile[ty + r][tx] = W[(size_t)(k0 + ty + r) * Dd + n0 + tx];
    __syncthreads();
#pragma unroll
    for (int r = 0; r < 32; r += 8)
        WT[(size_t)w * Dd * Dd + (size_t)(n0 + ty + r) * Dd + k0 + tx] =
            __float2half(tile[tx][ty + r]);
}

// ---------------- gather + layernorm -> half (single-pass stats) --------------
__global__ void k_gather_ln(const float* __restrict__ emb, const float* __restrict__ upd,
                            const int* __restrict__ idx, const float* __restrict__ sc,
                            const float* __restrict__ bi, __half* __restrict__ out, int NR) {
    __shared__ float2 p1[8];
    int tid = threadIdx.x, grp = tid >> 6, t = tid & 63, warp = tid >> 5, lane = tid & 31;
    int row = blockIdx.x * 4 + grp;
    int b = row / NR, i = row - b * NR;
    int id = idx[i];
    float4 e = ((const float4*)(emb + (size_t)id * Dd))[t];
    float4 u = ((const float4*)(upd + ((size_t)b * NS + id) * Dd))[t];
    float4 x = make_float4(e.x + u.x, e.y + u.y, e.z + u.z, e.w + u.w);
    float s1 = x.x + x.y + x.z + x.w;
    float s2 = x.x * x.x + x.y * x.y + x.z * x.z + x.w * x.w;
    float2 ss = gsum64x2(s1, s2, p1, warp, lane, grp);
    float m = ss.x * (1.f / 256.f);
    float var = ss.y * (1.f / 256.f) - m * m;
    float rs = rsqrtf(var + 1e-5f);
    float4 s4 = ((const float4*)sc)[t];
    float4 b4 = ((const float4*)bi)[t];
    __half2 h0 = __floats2half2_rn((x.x - m) * rs * s4.x + b4.x, (x.y - m) * rs * s4.y + b4.y);
    __half2 h1 = __floats2half2_rn((x.z - m) * rs * s4.z + b4.z, (x.w - m) * rs * s4.w + b4.w);
    uint2 pk; pk.x = h2u(h0); pk.y = h2u(h1);
    *(uint2*)&out[(size_t)row * Dd + 4 * t] = pk;
}

// ---------------- layernorm -> fp32 + half (single-pass stats) ----------------
__global__ void k_ln(const float* __restrict__ x, const float* __restrict__ sc,
                     const float* __restrict__ bi, float* __restrict__ outf,
                     __half* __restrict__ outh) {
    __shared__ float2 p1[8];
    int tid = threadIdx.x, grp = tid >> 6, t = tid & 63, warp = tid >> 5, lane = tid & 31;
    size_t row = blockIdx.x * 4 + grp;
    float4 v = ((const float4*)(x + row * Dd))[t];
    float s1 = v.x + v.y + v.z + v.w;
    float s2 = v.x * v.x + v.y * v.y + v.z * v.z + v.w * v.w;
    float2 ss = gsum64x2(s1, s2, p1, warp, lane, grp);
    float m = ss.x * (1.f / 256.f);
    float var = ss.y * (1.f / 256.f) - m * m;
    float rs = rsqrtf(var + 1e-5f);
    float4 s4 = ((const float4*)sc)[t];
    float4 b4 = ((const float4*)bi)[t];
    float4 y = make_float4((v.x - m) * rs * s4.x + b4.x, (v.y - m) * rs * s4.y + b4.y,
                           (v.z - m) * rs * s4.z + b4.z, (v.w - m) * rs * s4.w + b4.w);
    ((float4*)(outf + row * Dd))[t] = y;
    __half2 h0 = __floats2half2_rn(y.x, y.y);
    __half2 h1 = __floats2half2_rn(y.z, y.w);
    uint2 pk; pk.x = h2u(h0); pk.y = h2u(h1);
    *(uint2*)&outh[row * Dd + 4 * t] = pk;
}

// ---------------- fused double-LN + scatter-add (single-pass stats) -----------
__global__ void k_dln_scatter(const float* __restrict__ hb, const float* __restrict__ f,
                              const float* __restrict__ os, const float* __restrict__ ob,
                              const float* __restrict__ es, const float* __restrict__ eb,
                              const int* __restrict__ qi, float* __restrict__ upd) {
    __shared__ float2 p1[8], p2[8];
    int tid = threadIdx.x, grp = tid >> 6, t = tid & 63, warp = tid >> 5, lane = tid & 31;
    int row = blockIdx.x * 4 + grp;
    int b = row / NQ, q = row - b * NQ;
    float4 hv = ((const float4*)(hb + (size_t)row * Dd))[t];
    float4 fv = ((const float4*)(f + (size_t)row * Dd))[t];
    float4 x = make_float4(hv.x + fv.x, hv.y + fv.y, hv.z + fv.z, hv.w + fv.w);
    float s1 = x.x + x.y + x.z + x.w;
    float s2 = x.x * x.x + x.y * x.y + x.z * x.z + x.w * x.w;
    float2 ss = gsum64x2(s1, s2, p1, warp, lane, grp);
    float m = ss.x * (1.f / 256.f);
    float var = ss.y * (1.f / 256.f) - m * m;
    float rs = rsqrtf(var + 1e-5f);
    float4 s4 = ((const float4*)os)[t];
    float4 b4 = ((const float4*)ob)[t];
    float4 y = make_float4((x.x - m) * rs * s4.x + b4.x, (x.y - m) * rs * s4.y + b4.y,
                           (x.z - m) * rs * s4.z + b4.z, (x.w - m) * rs * s4.w + b4.w);
    s1 = y.x + y.y + y.z + y.w;
    s2 = y.x * y.x + y.y * y.y + y.z * y.z + y.w * y.w;
    ss = gsum64x2(s1, s2, p2, warp, lane, grp);
    m = ss.x * (1.f / 256.f);
    var = ss.y * (1.f / 256.f) - m * m;
    rs = rsqrtf(var + 1e-5f);
    s4 = ((const float4*)es)[t];
    b4 = ((const float4*)eb)[t];
    float r0 = (y.x - m) * rs * s4.x + b4.x, r1 = (y.y - m) * rs * s4.y + b4.y;
    float r2 = (y.z - m) * rs * s4.z + b4.z, r3 = (y.w - m) * rs * s4.w + b4.w;
    int id = qi[q];
    size_t o = ((size_t)b * NS + id) * Dd + t * 4;
    atomicAdd(&upd[o + 0], r0);
    atomicAdd(&upd[o + 1], r1);
    atomicAdd(&upd[o + 2], r2);
    atomicAdd(&upd[o + 3], r3);
}

// ---------------- fp16 MMA GEMM, 128x128 block tile, cp.async ------------------
// A: [M][256] half, WT: [256 n][256 k] half. 8 warps; warp = 16M x 128N.
// Smem: As 2x(128x72), Ws 2x(128x72) halves = 73728 B dynamic.
template <int ACT, int HOUT>
__global__ void __launch_bounds__(256)
proj_h(const __half* __restrict__ A, const __half* __restrict__ WT,
       const float* __restrict__ bias, __half* __restrict__ Ch,
       float* __restrict__ Cf) {
    extern __shared__ __half psm[];
    __half* As = psm;              // buf b at + b*9216
    __half* Ws = psm + 18432;      // buf b at + b*9216
    int m0 = blockIdx.x * 128, n0 = blockIdx.y * 128;
    int tid = threadIdx.x, warp = tid >> 5, lane = tid & 31;
    int g = lane >> 2, tg = lane & 3;
    int mw = warp * 16;
    float acc[16][4];
#pragma unroll
    for (int j = 0; j < 16; j++)
#pragma unroll
        for (int i = 0; i < 4; i++) acc[j][i] = 0.f;

    // prefetch stage 0 (A and W both 128 rows x 64 halves)
#pragma unroll
    for (int it = 0; it < 4; it++) {
        int i = tid + it * 256;
        int r = i >> 3, c8 = (i & 7) << 3;
        cp_async16(&As[r * 72 + c8], &A[(size_t)(m0 + r) * Dd + c8]);
        cp_async16(&Ws[r * 72 + c8], &WT[(size_t)(n0 + r) * Dd + c8]);
    }
    CP_COMMIT();

    int buf = 0;
    for (int ki = 0; ki < 4; ki++) {
        CP_WAIT0();
        __syncthreads();
        if (ki < 3) {
            int kc = (ki + 1) * 64;
            int nb = buf ^ 1;
#pragma unroll
            for (int it = 0; it < 4; it++) {
                int i = tid + it * 256;
                int r = i >> 3, c8 = (i & 7) << 3;
                cp_async16(&As[nb * 9216 + r * 72 + c8], &A[(size_t)(m0 + r) * Dd + kc + c8]);
                cp_async16(&Ws[nb * 9216 + r * 72 + c8], &WT[(size_t)(n0 + r) * Dd + kc + c8]);
            }
            CP_COMMIT();
        }
        const __half* Ab = As + buf * 9216;
        const __half* Wb = Ws + buf * 9216;
#pragma unroll
        for (int k16 = 0; k16 < 4; k16++) {
            int kk = k16 * 16;
            unsigned a0 = *(const unsigned*)&Ab[(mw + g) * 72 + kk + 2 * tg];
            unsigned a1 = *(const unsigned*)&Ab[(mw + g + 8) * 72 + kk + 2 * tg];
            unsigned a2 = *(const unsigned*)&Ab[(mw + g) * 72 + kk + 2 * tg + 8];
            unsigned a3 = *(const unsigned*)&Ab[(mw + g + 8) * 72 + kk + 2 * tg + 8];
#pragma unroll
            for (int j = 0; j < 16; j++) {
                unsigned b0 = *(const unsigned*)&Wb[(j * 8 + g) * 72 + kk + 2 * tg];
                unsigned b1 = *(const unsigned*)&Wb[(j * 8 + g) * 72 + kk + 2 * tg + 8];
                mma_f16(acc[j], a0, a1, a2, a3, b0, b1);
            }
        }
        buf ^= 1;
    }
#pragma unroll
    for (int j = 0; j < 16; j++) {
        int col = n0 + j * 8 + 2 * tg;
        float bv0 = bias ? bias[col] : 0.f;
        float bv1 = bias ? bias[col + 1] : 0.f;
        float v0 = acc[j][0] + bv0, v1 = acc[j][1] + bv1;
        float v2 = acc[j][2] + bv0, v3 = acc[j][3] + bv1;
        if (ACT) { v0 = gelu_tanh(v0); v1 = gelu_tanh(v1); v2 = gelu_tanh(v2); v3 = gelu_tanh(v3); }
        int r0 = m0 + mw + g;
        if (HOUT) {
            __half2 hA = __floats2half2_rn(v0, v1);
            __half2 hB = __floats2half2_rn(v2, v3);
            *(unsigned*)&Ch[(size_t)r0 * Dd + col] = h2u(hA);
            *(unsigned*)&Ch[(size_t)(r0 + 8) * Dd + col] = h2u(hB);
        } else {
            *(float2*)&Cf[(size_t)r0 * Dd + col] = make_float2(v0, v1);
            *(float2*)&Cf[(size_t)(r0 + 8) * Dd + col] = make_float2(v2, v3);
        }
    }
}

// ---------------- fused flash attention: cp.async K/V + register-resident P ---
// Smem: Q 128x72, K 2x(64x72), V 2x(64x72) halves = 55296 B dynamic.
__global__ void __launch_bounds__(256)
flash_attn(const __half* __restrict__ Q, const __half* __restrict__ K,
           const __half* __restrict__ V, const unsigned long long* __restrict__ mpk,
           __half* __restrict__ ctx) {
    extern __shared__ __half hsm[];
    __half* Qs = hsm;                // 128*72
    __half* Ks = hsm + 9216;         // 2 x 64*72
    __half* Vs = hsm + 18432;        // 2 x 64*72

    int bh = blockIdx.z;
    int b = bh >> 2, h = bh & 3;
    int q0 = blockIdx.x * 128;
    int tid = threadIdx.x, warp = tid >> 5, lane = tid & 31;
    int g = lane >> 2, tg = lane & 3;
    int mw = warp * 16;

    const __half* Qg = Q + ((size_t)(b * NQ + q0)) * Dd + h * DH;
    const __half* Kg = K + ((size_t)b * NK) * Dd + h * DH;
    const __half* Vg = V + ((size_t)b * NK) * Dd + h * DH;

#pragma unroll
    for (int it = 0; it < 4; it++) {
        int i = tid + it * 256;
        int r = i >> 3, c8 = (i & 7) << 3;
        *(uint4*)&Qs[r * 72 + c8] = *(const uint4*)&Qg[(size_t)r * Dd + c8];
    }
#pragma unroll
    for (int it = 0; it < 2; it++) {
        int i = tid + it * 256;
        int r = i >> 3, c8 = (i & 7) << 3;
        cp_async16(&Ks[r * 72 + c8], &Kg[(size_t)r * Dd + c8]);
        cp_async16(&Vs[r * 72 + c8], &Vg[(size_t)r * Dd + c8]);
    }
    CP_COMMIT();

    float O[8][4];
#pragma unroll
    for (int j = 0; j < 8; j++)
#pragma unroll
        for (int i = 0; i < 4; i++) O[j][i] = 0.f;
    float m0r = -3.0e38f, m1r = -3.0e38f, l0 = 0.f, l1 = 0.f;

    const unsigned long long* mp0 = mpk + (size_t)(q0 + mw + g) * 16;
    const unsigned long long* mp1 = mpk + (size_t)(q0 + mw + g + 8) * 16;

    int buf = 0;
    for (int kt = 0; kt < 16; kt++) {
        CP_WAIT0();
        __syncthreads();
        if (kt < 15) {
            int kb2 = (kt + 1) * 64;
            int nb = buf ^ 1;
#pragma unroll
            for (int it = 0; it < 2; it++) {
                int i = tid + it * 256;
                int r = i >> 3, c8 = (i & 7) << 3;
                cp_async16(&Ks[nb * 4608 + r * 72 + c8], &Kg[(size_t)(kb2 + r) * Dd + c8]);
                cp_async16(&Vs[nb * 4608 + r * 72 + c8], &Vg[(size_t)(kb2 + r) * Dd + c8]);
            }
            CP_COMMIT();
        }
        const __half* kbuf = Ks + buf * 4608;
        const __half* vbuf = Vs + buf * 4608;
        unsigned long long mb0 = mp0[kt];
        unsigned long long mb1 = mp1[kt];

        // S = Q @ K^T
        float s[8][4];
#pragma unroll
        for (int j = 0; j < 8; j++)
#pragma unroll
            for (int i = 0; i < 4; i++) s[j][i] = 0.f;
#pragma unroll
        for (int k16 = 0; k16 < 4; k16++) {
            int kk = k16 * 16;
            unsigned a0 = *(const unsigned*)&Qs[(mw + g) * 72 + kk + 2 * tg];
            unsigned a1 = *(const unsigned*)&Qs[(mw + g + 8) * 72 + kk + 2 * tg];
            unsigned a2 = *(const unsigned*)&Qs[(mw + g) * 72 + kk + 2 * tg + 8];
            unsigned a3 = *(const unsigned*)&Qs[(mw + g + 8) * 72 + kk + 2 * tg + 8];
#pragma unroll
            for (int j = 0; j < 8; j++) {
                unsigned b0 = *(const unsigned*)&kbuf[(j * 8 + g) * 72 + kk + 2 * tg];
                unsigned b1 = *(const unsigned*)&kbuf[(j * 8 + g) * 72 + kk + 2 * tg + 8];
                mma_f16(s[j], a0, a1, a2, a3, b0, b1);
            }
        }

        // scale + bitmask + row max
        float mx0 = -3.0e38f, mx1 = -3.0e38f;
#pragma unroll
        for (int j = 0; j < 8; j++) {
            int c = j * 8 + 2 * tg;
            s[j][0] = ((mb0 >> c) & 1ull) ? s[j][0] * ATTN_SCALE : -1e9f;
            s[j][1] = ((mb0 >> (c + 1)) & 1ull) ? s[j][1] * ATTN_SCALE : -1e9f;
            s[j][2] = ((mb1 >> c) & 1ull) ? s[j][2] * ATTN_SCALE : -1e9f;
            s[j][3] = ((mb1 >> (c + 1)) & 1ull) ? s[j][3] * ATTN_SCALE : -1e9f;
            mx0 = fmaxf(mx0, fmaxf(s[j][0], s[j][1]));
            mx1 = fmaxf(mx1, fmaxf(s[j][2], s[j][3]));
        }
        mx0 = fmaxf(mx0, __shfl_xor_sync(0xffffffffu, mx0, 1));
        mx0 = fmaxf(mx0, __shfl_xor_sync(0xffffffffu, mx0, 2));
        mx1 = fmaxf(mx1, __shfl_xor_sync(0xffffffffu, mx1, 1));
        mx1 = fmaxf(mx1, __shfl_xor_sync(0xffffffffu, mx1, 2));

        float mn0 = fmaxf(m0r, mx0), mn1 = fmaxf(m1r, mx1);
        float al0 = __expf(m0r - mn0), al1 = __expf(m1r - mn1);
        m0r = mn0; m1r = mn1;

        // exp -> P kept in registers (PV A-fragments)
        unsigned ph[8][2];
        float rs0 = 0.f, rs1 = 0.f;
#pragma unroll
        for (int j = 0; j < 8; j++) {
            float p0 = __expf(s[j][0] - mn0), p1 = __expf(s[j][1] - mn0);
            float p2 = __expf(s[j][2] - mn1), p3 = __expf(s[j][3] - mn1);
            rs0 += p0 + p1; rs1 += p2 + p3;
            ph[j][0] = h2u(__floats2half2_rn(p0, p1));
            ph[j][1] = h2u(__floats2half2_rn(p2, p3));
        }
        rs0 += __shfl_xor_sync(0xffffffffu, rs0, 1);
        rs0 += __shfl_xor_sync(0xffffffffu, rs0, 2);
        rs1 += __shfl_xor_sync(0xffffffffu, rs1, 1);
        rs1 += __shfl_xor_sync(0xffffffffu, rs1, 2);
        l0 = l0 * al0 + rs0;
        l1 = l1 * al1 + rs1;
#pragma unroll
        for (int j = 0; j < 8; j++) {
            O[j][0] *= al0; O[j][1] *= al0; O[j][2] *= al1; O[j][3] *= al1;
        }

        // O += P @ V
#pragma unroll
        for (int k16 = 0; k16 < 4; k16++) {
            int kk = k16 * 16;
            unsigned a0 = ph[2 * k16][0];
            unsigned a1 = ph[2 * k16][1];
            unsigned a2 = ph[2 * k16 + 1][0];
            unsigned a3 = ph[2 * k16 + 1][1];
            int vrow = kk + (lane & 7) + ((lane >> 3) & 1) * 8;
#pragma unroll
            for (int j = 0; j < 8; j++) {
                unsigned b0, b1;
                unsigned saddr = (unsigned)__cvta_generic_to_shared(&vbuf[vrow * 72 + j * 8]);
                asm volatile("ldmatrix.sync.aligned.m8n8.x2.trans.shared.b16 {%0,%1}, [%2];"
                             : "=r"(b0), "=r"(b1) : "r"(saddr));
                mma_f16(O[j], a0, a1, a2, a3, b0, b1);
            }
        }
        buf ^= 1;
    }

    float inv0 = 1.f / l0, inv1 = 1.f / l1;
    __half* og = ctx + ((size_t)(b * NQ + q0)) * Dd + h * DH;
#pragma unroll
    for (int j = 0; j < 8; j++) {
        int col = j * 8 + 2 * tg;
        __half2 h0 = __floats2half2_rn(O[j][0] * inv0, O[j][1] * inv0);
        __half2 h1 = __floats2half2_rn(O[j][2] * inv1, O[j][3] * inv1);
        *(unsigned*)&og[(size_t)(mw + g) * Dd + col] = h2u(h0);
        *(unsigned*)&og[(size_t)(mw + g + 8) * Dd + col] = h2u(h1);
    }
}

// ---------------- launch ------------------------------------------------------
extern "C" void kernel_launch(void* const* d_in, const int* in_sizes, int n_in,
                              void* d_out, int out_size) {
    const float* upd_in = (const float*)d_in[0];
    const float* emb    = (const float*)d_in[1];
    const float* mask   = (const float*)d_in[2];
    const float* Wq     = (const float*)d_in[3];
    const float* Wk     = (const float*)d_in[4];
    const float* Wv     = (const float*)d_in[5];
    const float* Wo     = (const float*)d_in[6];
    const float* W1     = (const float*)d_in[7];
    const float* b1     = (const float*)d_in[8];
    const float* W2     = (const float*)d_in[9];
    const float* b2     = (const float*)d_in[10];
    const float* sys_s  = (const float*)d_in[11];
    const float* sys_b  = (const float*)d_in[12];
    const float* eff_s  = (const float*)d_in[13];
    const float* eff_b  = (const float*)d_in[14];
    const float* in_s   = (const float*)d_in[15];
    const float* in_b   = (const float*)d_in[16];
    const float* out_s  = (const float*)d_in[17];
    const float* out_b  = (const float*)d_in[18];
    const int*   qidx   = (const int*)d_in[19];
    const int*   kidx   = (const int*)d_in[20];
    float* out = (float*)d_out;

    float *upd, *hb, *t1f, *t2;
    __half *qh, *kh, *Qh, *Kh, *Vh, *ctxh, *hh, *t1h, *WT;
    unsigned long long* mpk;
    cudaGetSymbolAddress((void**)&upd,  g_upd);
    cudaGetSymbolAddress((void**)&hb,   g_hb);
    cudaGetSymbolAddress((void**)&t1f,  g_t1f);
    cudaGetSymbolAddress((void**)&t2,   g_t2);
    cudaGetSymbolAddress((void**)&qh,   g_qh);
    cudaGetSymbolAddress((void**)&kh,   g_kh);
    cudaGetSymbolAddress((void**)&Qh,   g_Qh);
    cudaGetSymbolAddress((void**)&Kh,   g_Kh);
    cudaGetSymbolAddress((void**)&Vh,   g_Vh);
    cudaGetSymbolAddress((void**)&ctxh, g_ctxh);
    cudaGetSymbolAddress((void**)&hh,   g_hh);
    cudaGetSymbolAddress((void**)&t1h,  g_t1h);
    cudaGetSymbolAddress((void**)&WT,   g_WT);
    cudaGetSymbolAddress((void**)&mpk,  g_mpk);

    cudaFuncSetAttribute(flash_attn, cudaFuncAttributeMaxDynamicSharedMemorySize, 55296);
    cudaFuncSetAttribute(proj_h<0, 1>, cudaFuncAttributeMaxDynamicSharedMemorySize, 73728);
    cudaFuncSetAttribute(proj_h<0, 0>, cudaFuncAttributeMaxDynamicSharedMemorySize, 73728);
    cudaFuncSetAttribute(proj_h<1, 1>, cudaFuncAttributeMaxDynamicSharedMemorySize, 73728);

    int n_upd = Bb * NS * Dd;
    k_init<<<8192, 256>>>(upd_in, upd, n_upd);
    k_prep<<<dim3(8, 8, 6), dim3(32, 8)>>>(Wq, Wk, Wv, Wo, W1, W2, WT);
    k_maskpack<<<(Ll * NQ * 16 + 255) / 256, 256>>>(mask, mpk);

    const int DD2 = Dd * Dd;
    for (int l = 0; l < Ll; l++) {
        const unsigned long long* mpk_l = mpk + (size_t)l * NQ * 16;
        const int* qi = qidx + l * NQ;
        const int* ki = kidx + l * NK;

        k_gather_ln<<<Bb * NQ / 4, 256>>>(emb, upd, qi, sys_s, sys_b, qh, NQ);
        k_gather_ln<<<Bb * NK / 4, 256>>>(emb, upd, ki, sys_s, sys_b, kh, NK);

        proj_h<0, 1><<<dim3(128, 2), 256, 73728>>>(qh, WT + 0 * DD2, nullptr, Qh, nullptr);
        proj_h<0, 1><<<dim3(256, 2), 256, 73728>>>(kh, WT + 1 * DD2, nullptr, Kh, nullptr);
        proj_h<0, 1><<<dim3(256, 2), 256, 73728>>>(kh, WT + 2 * DD2, nullptr, Vh, nullptr);

        flash_attn<<<dim3(NQ / 128, 1, Bb * Hh), 256, 55296>>>(Qh, Kh, Vh, mpk_l, ctxh);

        proj_h<0, 0><<<dim3(128, 2), 256, 73728>>>(ctxh, WT + 3 * DD2, nullptr, nullptr, t1f);
        k_ln<<<Bb * NQ / 4, 256>>>(t1f, in_s, in_b, hb, hh);

        proj_h<1, 1><<<dim3(128, 2), 256, 73728>>>(hh, WT + 4 * DD2, b1, t1h, nullptr);
        proj_h<0, 0><<<dim3(128, 2), 256, 73728>>>(t1h, WT + 5 * DD2, b2, nullptr, t2);

        k_dln_scatter<<<Bb * NQ / 4, 256>>>(hb, t2, out_s, out_b, eff_s, eff_b, qi, upd);
    }
    k_final<<<8192, 256>>>(upd, upd_in, out, n_upd);
}

// round 16
// speedup vs baseline: 1.5031x; 1.5031x over previous
#include <cuda_runtime.h>
#include <cuda_fp16.h>
#include <math.h>

#define Bb 32
#define NS 4096
#define Dd 256
#define Hh 4
#define Ll 6
#define NQ 512
#define NK 1024
#define DH 64
#define ATTN_SCALE 0.125f

// ---------------- scratch (static device globals; no allocation) -------------
__device__ float  g_upd[Bb * NS * Dd];
__device__ float  g_hb [Bb * NQ * Dd];
__device__ float  g_t1f[Bb * NQ * Dd];
__device__ float  g_t2 [Bb * NQ * Dd];
__device__ __half g_qh [Bb * NQ * Dd];
__device__ __half g_kh [Bb * NK * Dd];
__device__ __half g_Qh [Bb * NQ * Dd];
__device__ __half g_Kh [Bb * NK * Dd];
__device__ __half g_Vh [Bb * NK * Dd];
__device__ __half g_ctxh[Bb * NQ * Dd];
__device__ __half g_hh [Bb * NQ * Dd];
__device__ __half g_t1h[Bb * NQ * Dd];
__device__ __half g_WT [6 * Dd * Dd];                  // transposed half weights [n][k]
__device__ unsigned long long g_mpk[Ll * NQ * 16];     // bit-packed masks

// ---------------- helpers ----------------------------------------------------
__device__ __forceinline__ float gelu_tanh(float x) {
    float x3 = x * x * x;
    return 0.5f * x * (1.f + tanhf(0.7978845608028654f * (x + 0.044715f * x3)));
}

__device__ __forceinline__ unsigned h2u(__half2 h) {
    return *reinterpret_cast<unsigned*>(&h);
}

__device__ __forceinline__ void mma_f16(float c[4], unsigned a0, unsigned a1,
                                        unsigned a2, unsigned a3,
                                        unsigned b0, unsigned b1) {
    asm volatile(
        "mma.sync.aligned.m16n8k16.row.col.f32.f16.f16.f32 "
        "{%0,%1,%2,%3}, {%4,%5,%6,%7}, {%8,%9}, {%0,%1,%2,%3};"
        : "+f"(c[0]), "+f"(c[1]), "+f"(c[2]), "+f"(c[3])
        : "r"(a0), "r"(a1), "r"(a2), "r"(a3), "r"(b0), "r"(b1));
}

__device__ __forceinline__ void cp_async16(__half* smem, const __half* gmem) {
    unsigned s = (unsigned)__cvta_generic_to_shared(smem);
    asm volatile("cp.async.cg.shared.global [%0], [%1], 16;" :: "r"(s), "l"(gmem));
}
#define CP_COMMIT() asm volatile("cp.async.commit_group;")
#define CP_WAIT0()  asm volatile("cp.async.wait_group 0;")

// two-value (sum, sumsq) 64-thread-group reduction; one sync round
__device__ __forceinline__ float2 gsum64x2(float a, float b, float2* part,
                                           int warp, int lane, int grp) {
#pragma unroll
    for (int o = 16; o; o >>= 1) {
        a += __shfl_xor_sync(0xffffffffu, a, o);
        b += __shfl_xor_sync(0xffffffffu, b, o);
    }
    if (lane == 0) part[warp] = make_float2(a, b);
    __syncthreads();
    float2 r0 = part[2 * grp], r1 = part[2 * grp + 1];
    return make_float2(r0.x + r1.x, r0.y + r1.y);
}

// ---------------- init: upd = copy(src) ---------------------------------------
__global__ void k_init(const float* __restrict__ src, float* __restrict__ upd, int n) {
    for (int i = blockIdx.x * blockDim.x + threadIdx.x; i < n; i += gridDim.x * blockDim.x)
        upd[i] = src[i];
}

// ---------------- final: out = upd - upd_in -----------------------------------
__global__ void k_final(const float* __restrict__ upd, const float* __restrict__ src,
                        float* __restrict__ out, int n) {
    for (int i = blockIdx.x * blockDim.x + threadIdx.x; i < n; i += gridDim.x * blockDim.x)
        out[i] = upd[i] - src[i];
}

// ---------------- pack masks into bits: mp[l][q][kt] --------------------------
__global__ void k_maskpack(const float* __restrict__ mask, unsigned long long* __restrict__ mp) {
    int w = blockIdx.x * blockDim.x + threadIdx.x;
    if (w >= Ll * NQ * 16) return;
    int kt = w & 15, q = (w >> 4) & (NQ - 1), l = w >> 13;
    const float* src = mask + ((size_t)l * NQ + q) * NK + kt * 64;
    unsigned long long bits = 0;
#pragma unroll
    for (int c = 0; c < 64; c += 4) {
        float4 v = *(const float4*)&src[c];
        bits |= ((unsigned long long)(v.x > 0.5f)) << c;
        bits |= ((unsigned long long)(v.y > 0.5f)) << (c + 1);
        bits |= ((unsigned long long)(v.z > 0.5f)) << (c + 2);
        bits |= ((unsigned long long)(v.w > 0.5f)) << (c + 3);
    }
    mp[w] = bits;
}

// ---------------- weight transpose + fp16 convert (once per launch) -----------
__global__ void k_prep(const float* __restrict__ Wq, const float* __restrict__ Wk,
                       const float* __restrict__ Wv, const float* __restrict__ Wo,
                       const float* __restrict__ W1, const float* __restrict__ W2,
                       __half* __restrict__ WT) {
    __shared__ float tile[32][33];
    int w = blockIdx.z;
    const float* W = (w == 0) ? Wq : (w == 1) ? Wk : (w == 2) ? Wv
                   : (w == 3) ? Wo : (w == 4) ? W1 : W2;
    int k0 = blockIdx.x * 32, n0 = blockIdx.y * 32;
    int tx = threadIdx.x, ty = threadIdx.y;
#pragma unroll
    for (int r = 0; r < 32; r += 8)
        tile[ty + r][tx] = W[(size_t)(k0 + ty + r) * Dd + n0 + tx];
    __syncthreads();
#pragma unroll
    for (int r = 0; r < 32; r += 8)
        WT[(size_t)w * Dd * Dd + (size_t)(n0 + ty + r) * Dd + k0 + tx] =
            __float2half(tile[tx][ty + r]);
}

// ------ fused gather+LN for q AND k sides in one launch (single-pass stats) ---
__global__ void k_gather_ln2(const float* __restrict__ emb, const float* __restrict__ upd,
                             const int* __restrict__ qidx, const int* __restrict__ kidx,
                             const float* __restrict__ sc, const float* __restrict__ bi,
                             __half* __restrict__ qout, __half* __restrict__ kout) {
    __shared__ float2 p1[8];
    int tid = threadIdx.x, grp = tid >> 6, t = tid & 63, warp = tid >> 5, lane = tid & 31;
    int row = blockIdx.x * 4 + grp;
    const int* idx;
    __half* out;
    int NR, lrow;
    if (row < Bb * NQ) { idx = qidx; out = qout; NR = NQ; lrow = row; }
    else { idx = kidx; out = kout; NR = NK; lrow = row - Bb * NQ; }
    int b = lrow / NR, i = lrow - b * NR;
    int id = idx[i];
    float4 e = ((const float4*)(emb + (size_t)id * Dd))[t];
    float4 u = ((const float4*)(upd + ((size_t)b * NS + id) * Dd))[t];
    float4 x = make_float4(e.x + u.x, e.y + u.y, e.z + u.z, e.w + u.w);
    float s1 = x.x + x.y + x.z + x.w;
    float s2 = x.x * x.x + x.y * x.y + x.z * x.z + x.w * x.w;
    float2 ss = gsum64x2(s1, s2, p1, warp, lane, grp);
    float m = ss.x * (1.f / 256.f);
    float var = ss.y * (1.f / 256.f) - m * m;
    float rs = rsqrtf(var + 1e-5f);
    float4 s4 = ((const float4*)sc)[t];
    float4 b4 = ((const float4*)bi)[t];
    __half2 h0 = __floats2half2_rn((x.x - m) * rs * s4.x + b4.x, (x.y - m) * rs * s4.y + b4.y);
    __half2 h1 = __floats2half2_rn((x.z - m) * rs * s4.z + b4.z, (x.w - m) * rs * s4.w + b4.w);
    uint2 pk; pk.x = h2u(h0); pk.y = h2u(h1);
    *(uint2*)&out[(size_t)lrow * Dd + 4 * t] = pk;
}

// ---------------- layernorm -> fp32 + half (single-pass stats) ----------------
__global__ void k_ln(const float* __restrict__ x, const float* __restrict__ sc,
                     const float* __restrict__ bi, float* __restrict__ outf,
                     __half* __restrict__ outh) {
    __shared__ float2 p1[8];
    int tid = threadIdx.x, grp = tid >> 6, t = tid & 63, warp = tid >> 5, lane = tid & 31;
    size_t row = blockIdx.x * 4 + grp;
    float4 v = ((const float4*)(x + row * Dd))[t];
    float s1 = v.x + v.y + v.z + v.w;
    float s2 = v.x * v.x + v.y * v.y + v.z * v.z + v.w * v.w;
    float2 ss = gsum64x2(s1, s2, p1, warp, lane, grp);
    float m = ss.x * (1.f / 256.f);
    float var = ss.y * (1.f / 256.f) - m * m;
    float rs = rsqrtf(var + 1e-5f);
    float4 s4 = ((const float4*)sc)[t];
    float4 b4 = ((const float4*)bi)[t];
    float4 y = make_float4((v.x - m) * rs * s4.x + b4.x, (v.y - m) * rs * s4.y + b4.y,
                           (v.z - m) * rs * s4.z + b4.z, (v.w - m) * rs * s4.w + b4.w);
    ((float4*)(outf + row * Dd))[t] = y;
    __half2 h0 = __floats2half2_rn(y.x, y.y);
    __half2 h1 = __floats2half2_rn(y.z, y.w);
    uint2 pk; pk.x = h2u(h0); pk.y = h2u(h1);
    *(uint2*)&outh[row * Dd + 4 * t] = pk;
}

// ---------------- fused double-LN + scatter-add (single-pass stats) -----------
__global__ void k_dln_scatter(const float* __restrict__ hb, const float* __restrict__ f,
                              const float* __restrict__ os, const float* __restrict__ ob,
                              const float* __restrict__ es, const float* __restrict__ eb,
                              const int* __restrict__ qi, float* __restrict__ upd) {
    __shared__ float2 p1[8], p2[8];
    int tid = threadIdx.x, grp = tid >> 6, t = tid & 63, warp = tid >> 5, lane = tid & 31;
    int row = blockIdx.x * 4 + grp;
    int b = row / NQ, q = row - b * NQ;
    float4 hv = ((const float4*)(hb + (size_t)row * Dd))[t];
    float4 fv = ((const float4*)(f + (size_t)row * Dd))[t];
    float4 x = make_float4(hv.x + fv.x, hv.y + fv.y, hv.z + fv.z, hv.w + fv.w);
    float s1 = x.x + x.y + x.z + x.w;
    float s2 = x.x * x.x + x.y * x.y + x.z * x.z + x.w * x.w;
    float2 ss = gsum64x2(s1, s2, p1, warp, lane, grp);
    float m = ss.x * (1.f / 256.f);
    float var = ss.y * (1.f / 256.f) - m * m;
    float rs = rsqrtf(var + 1e-5f);
    float4 s4 = ((const float4*)os)[t];
    float4 b4 = ((const float4*)ob)[t];
    float4 y = make_float4((x.x - m) * rs * s4.x + b4.x, (x.y - m) * rs * s4.y + b4.y,
                           (x.z - m) * rs * s4.z + b4.z, (x.w - m) * rs * s4.w + b4.w);
    s1 = y.x + y.y + y.z + y.w;
    s2 = y.x * y.x + y.y * y.y + y.z * y.z + y.w * y.w;
    ss = gsum64x2(s1, s2, p2, warp, lane, grp);
    m = ss.x * (1.f / 256.f);
    var = ss.y * (1.f / 256.f) - m * m;
    rs = rsqrtf(var + 1e-5f);
    s4 = ((const float4*)es)[t];
    b4 = ((const float4*)eb)[t];
    float r0 = (y.x - m) * rs * s4.x + b4.x, r1 = (y.y - m) * rs * s4.y + b4.y;
    float r2 = (y.z - m) * rs * s4.z + b4.z, r3 = (y.w - m) * rs * s4.w + b4.w;
    int id = qi[q];
    size_t o = ((size_t)b * NS + id) * Dd + t * 4;
    atomicAdd(&upd[o + 0], r0);
    atomicAdd(&upd[o + 1], r1);
    atomicAdd(&upd[o + 2], r2);
    atomicAdd(&upd[o + 3], r3);
}

// ---------------- fp16 MMA GEMM core (128x64 tile, cp.async) ------------------
template <int ACT, int HOUT>
__device__ __forceinline__ void proj_body(
    const __half* __restrict__ A, const __half* __restrict__ WT,
    const float* __restrict__ bias, __half* __restrict__ Ch,
    float* __restrict__ Cf, int m0, int n0, __half* psm) {
    __half* As = psm;              // buf b at + b*9216
    __half* Ws = psm + 18432;      // buf b at + b*4608
    int tid = threadIdx.x, warp = tid >> 5, lane = tid & 31;
    int g = lane >> 2, tg = lane & 3;
    int mw = warp * 16;
    float acc[8][4];
#pragma unroll
    for (int j = 0; j < 8; j++)
#pragma unroll
        for (int i = 0; i < 4; i++) acc[j][i] = 0.f;

#pragma unroll
    for (int it = 0; it < 4; it++) {
        int i = tid + it * 256;
        int r = i >> 3, c8 = (i & 7) << 3;
        cp_async16(&As[r * 72 + c8], &A[(size_t)(m0 + r) * Dd + c8]);
    }
#pragma unroll
    for (int it = 0; it < 2; it++) {
        int i = tid + it * 256;
        int r = i >> 3, c8 = (i & 7) << 3;
        cp_async16(&Ws[r * 72 + c8], &WT[(size_t)(n0 + r) * Dd + c8]);
    }
    CP_COMMIT();

    int buf = 0;
    for (int ki = 0; ki < 4; ki++) {
        CP_WAIT0();
        __syncthreads();
        if (ki < 3) {
            int kc = (ki + 1) * 64;
            int nb = buf ^ 1;
#pragma unroll
            for (int it = 0; it < 4; it++) {
                int i = tid + it * 256;
                int r = i >> 3, c8 = (i & 7) << 3;
                cp_async16(&As[nb * 9216 + r * 72 + c8], &A[(size_t)(m0 + r) * Dd + kc + c8]);
            }
#pragma unroll
            for (int it = 0; it < 2; it++) {
                int i = tid + it * 256;
                int r = i >> 3, c8 = (i & 7) << 3;
                cp_async16(&Ws[nb * 4608 + r * 72 + c8], &WT[(size_t)(n0 + r) * Dd + kc + c8]);
            }
            CP_COMMIT();
        }
        const __half* Ab = As + buf * 9216;
        const __half* Wb = Ws + buf * 4608;
#pragma unroll
        for (int k16 = 0; k16 < 4; k16++) {
            int kk = k16 * 16;
            unsigned a0 = *(const unsigned*)&Ab[(mw + g) * 72 + kk + 2 * tg];
            unsigned a1 = *(const unsigned*)&Ab[(mw + g + 8) * 72 + kk + 2 * tg];
            unsigned a2 = *(const unsigned*)&Ab[(mw + g) * 72 + kk + 2 * tg + 8];
            unsigned a3 = *(const unsigned*)&Ab[(mw + g + 8) * 72 + kk + 2 * tg + 8];
#pragma unroll
            for (int j = 0; j < 8; j++) {
                unsigned b0 = *(const unsigned*)&Wb[(j * 8 + g) * 72 + kk + 2 * tg];
                unsigned b1 = *(const unsigned*)&Wb[(j * 8 + g) * 72 + kk + 2 * tg + 8];
                mma_f16(acc[j], a0, a1, a2, a3, b0, b1);
            }
        }
        buf ^= 1;
    }
#pragma unroll
    for (int j = 0; j < 8; j++) {
        int col = n0 + j * 8 + 2 * tg;
        float bv0 = bias ? bias[col] : 0.f;
        float bv1 = bias ? bias[col + 1] : 0.f;
        float v0 = acc[j][0] + bv0, v1 = acc[j][1] + bv1;
        float v2 = acc[j][2] + bv0, v3 = acc[j][3] + bv1;
        if (ACT) { v0 = gelu_tanh(v0); v1 = gelu_tanh(v1); v2 = gelu_tanh(v2); v3 = gelu_tanh(v3); }
        int r0 = m0 + mw + g;
        if (HOUT) {
            __half2 hA = __floats2half2_rn(v0, v1);
            __half2 hB = __floats2half2_rn(v2, v3);
            *(unsigned*)&Ch[(size_t)r0 * Dd + col] = h2u(hA);
            *(unsigned*)&Ch[(size_t)(r0 + 8) * Dd + col] = h2u(hB);
        } else {
            *(float2*)&Cf[(size_t)r0 * Dd + col] = make_float2(v0, v1);
            *(float2*)&Cf[(size_t)(r0 + 8) * Dd + col] = make_float2(v2, v3);
        }
    }
}

// generic single-GEMM wrapper
template <int ACT, int HOUT>
__global__ void __launch_bounds__(256)
proj_h(const __half* __restrict__ A, const __half* __restrict__ WT,
       const float* __restrict__ bias, __half* __restrict__ Ch,
       float* __restrict__ Cf) {
    extern __shared__ __half psm[];
    proj_body<ACT, HOUT>(A, WT, bias, Ch, Cf, blockIdx.x * 128, blockIdx.y * 64, psm);
}

// fused QKV projection: z=0 Q (qh, 128 m-blocks), z=1 K, z=2 V (kh, 256 m-blocks)
__global__ void __launch_bounds__(256)
proj_qkv(const __half* __restrict__ qh, const __half* __restrict__ kh,
         const __half* __restrict__ WT, __half* __restrict__ Qh,
         __half* __restrict__ Kh, __half* __restrict__ Vh) {
    extern __shared__ __half psm[];
    int z = blockIdx.z;
    if (z == 0 && blockIdx.x >= 128) return;
    const __half* A = (z == 0) ? qh : kh;
    const __half* W = WT + (size_t)z * Dd * Dd;
    __half* C = (z == 0) ? Qh : (z == 1) ? Kh : Vh;
    proj_body<0, 1>(A, W, nullptr, C, nullptr, blockIdx.x * 128, blockIdx.y * 64, psm);
}

// ---------------- fused flash attention: cp.async K/V + register-resident P ---
__global__ void __launch_bounds__(256)
flash_attn(const __half* __restrict__ Q, const __half* __restrict__ K,
           const __half* __restrict__ V, const unsigned long long* __restrict__ mpk,
           __half* __restrict__ ctx) {
    extern __shared__ __half hsm[];
    __half* Qs = hsm;                // 128*72
    __half* Ks = hsm + 9216;         // 2 x 64*72
    __half* Vs = hsm + 18432;        // 2 x 64*72

    int bh = blockIdx.z;
    int b = bh >> 2, h = bh & 3;
    int q0 = blockIdx.x * 128;
    int tid = threadIdx.x, warp = tid >> 5, lane = tid & 31;
    int g = lane >> 2, tg = lane & 3;
    int mw = warp * 16;

    const __half* Qg = Q + ((size_t)(b * NQ + q0)) * Dd + h * DH;
    const __half* Kg = K + ((size_t)b * NK) * Dd + h * DH;
    const __half* Vg = V + ((size_t)b * NK) * Dd + h * DH;

#pragma unroll
    for (int it = 0; it < 4; it++) {
        int i = tid + it * 256;
        int r = i >> 3, c8 = (i & 7) << 3;
        *(uint4*)&Qs[r * 72 + c8] = *(const uint4*)&Qg[(size_t)r * Dd + c8];
    }
#pragma unroll
    for (int it = 0; it < 2; it++) {
        int i = tid + it * 256;
        int r = i >> 3, c8 = (i & 7) << 3;
        cp_async16(&Ks[r * 72 + c8], &Kg[(size_t)r * Dd + c8]);
        cp_async16(&Vs[r * 72 + c8], &Vg[(size_t)r * Dd + c8]);
    }
    CP_COMMIT();

    float O[8][4];
#pragma unroll
    for (int j = 0; j < 8; j++)
#pragma unroll
        for (int i = 0; i < 4; i++) O[j][i] = 0.f;
    float m0r = -3.0e38f, m1r = -3.0e38f, l0 = 0.f, l1 = 0.f;

    const unsigned long long* mp0 = mpk + (size_t)(q0 + mw + g) * 16;
    const unsigned long long* mp1 = mpk + (size_t)(q0 + mw + g + 8) * 16;

    int buf = 0;
    for (int kt = 0; kt < 16; kt++) {
        CP_WAIT0();
        __syncthreads();
        if (kt < 15) {
            int kb2 = (kt + 1) * 64;
            int nb = buf ^ 1;
#pragma unroll
            for (int it = 0; it < 2; it++) {
                int i = tid + it * 256;
                int r = i >> 3, c8 = (i & 7) << 3;
                cp_async16(&Ks[nb * 4608 + r * 72 + c8], &Kg[(size_t)(kb2 + r) * Dd + c8]);
                cp_async16(&Vs[nb * 4608 + r * 72 + c8], &Vg[(size_t)(kb2 + r) * Dd + c8]);
            }
            CP_COMMIT();
        }
        const __half* kbuf = Ks + buf * 4608;
        const __half* vbuf = Vs + buf * 4608;
        unsigned long long mb0 = mp0[kt];
        unsigned long long mb1 = mp1[kt];

        // S = Q @ K^T
        float s[8][4];
#pragma unroll
        for (int j = 0; j < 8; j++)
#pragma unroll
            for (int i = 0; i < 4; i++) s[j][i] = 0.f;
#pragma unroll
        for (int k16 = 0; k16 < 4; k16++) {
            int kk = k16 * 16;
            unsigned a0 = *(const unsigned*)&Qs[(mw + g) * 72 + kk + 2 * tg];
            unsigned a1 = *(const unsigned*)&Qs[(mw + g + 8) * 72 + kk + 2 * tg];
            unsigned a2 = *(const unsigned*)&Qs[(mw + g) * 72 + kk + 2 * tg + 8];
            unsigned a3 = *(const unsigned*)&Qs[(mw + g + 8) * 72 + kk + 2 * tg + 8];
#pragma unroll
            for (int j = 0; j < 8; j++) {
                unsigned b0 = *(const unsigned*)&kbuf[(j * 8 + g) * 72 + kk + 2 * tg];
                unsigned b1 = *(const unsigned*)&kbuf[(j * 8 + g) * 72 + kk + 2 * tg + 8];
                mma_f16(s[j], a0, a1, a2, a3, b0, b1);
            }
        }

        // scale + bitmask + row max
        float mx0 = -3.0e38f, mx1 = -3.0e38f;
#pragma unroll
        for (int j = 0; j < 8; j++) {
            int c = j * 8 + 2 * tg;
            s[j][0] = ((mb0 >> c) & 1ull) ? s[j][0] * ATTN_SCALE : -1e9f;
            s[j][1] = ((mb0 >> (c + 1)) & 1ull) ? s[j][1] * ATTN_SCALE : -1e9f;
            s[j][2] = ((mb1 >> c) & 1ull) ? s[j][2] * ATTN_SCALE : -1e9f;
            s[j][3] = ((mb1 >> (c + 1)) & 1ull) ? s[j][3] * ATTN_SCALE : -1e9f;
            mx0 = fmaxf(mx0, fmaxf(s[j][0], s[j][1]));
            mx1 = fmaxf(mx1, fmaxf(s[j][2], s[j][3]));
        }
        mx0 = fmaxf(mx0, __shfl_xor_sync(0xffffffffu, mx0, 1));
        mx0 = fmaxf(mx0, __shfl_xor_sync(0xffffffffu, mx0, 2));
        mx1 = fmaxf(mx1, __shfl_xor_sync(0xffffffffu, mx1, 1));
        mx1 = fmaxf(mx1, __shfl_xor_sync(0xffffffffu, mx1, 2));

        float mn0 = fmaxf(m0r, mx0), mn1 = fmaxf(m1r, mx1);
        float al0 = __expf(m0r - mn0), al1 = __expf(m1r - mn1);
        m0r = mn0; m1r = mn1;

        // exp -> P kept in registers (PV A-fragments)
        unsigned ph[8][2];
        float rs0 = 0.f, rs1 = 0.f;
#pragma unroll
        for (int j = 0; j < 8; j++) {
            float p0 = __expf(s[j][0] - mn0), p1 = __expf(s[j][1] - mn0);
            float p2 = __expf(s[j][2] - mn1), p3 = __expf(s[j][3] - mn1);
            rs0 += p0 + p1; rs1 += p2 + p3;
            ph[j][0] = h2u(__floats2half2_rn(p0, p1));
            ph[j][1] = h2u(__floats2half2_rn(p2, p3));
        }
        rs0 += __shfl_xor_sync(0xffffffffu, rs0, 1);
        rs0 += __shfl_xor_sync(0xffffffffu, rs0, 2);
        rs1 += __shfl_xor_sync(0xffffffffu, rs1, 1);
        rs1 += __shfl_xor_sync(0xffffffffu, rs1, 2);
        l0 = l0 * al0 + rs0;
        l1 = l1 * al1 + rs1;
#pragma unroll
        for (int j = 0; j < 8; j++) {
            O[j][0] *= al0; O[j][1] *= al0; O[j][2] *= al1; O[j][3] *= al1;
        }

        // O += P @ V
#pragma unroll
        for (int k16 = 0; k16 < 4; k16++) {
            int kk = k16 * 16;
            unsigned a0 = ph[2 * k16][0];
            unsigned a1 = ph[2 * k16][1];
            unsigned a2 = ph[2 * k16 + 1][0];
            unsigned a3 = ph[2 * k16 + 1][1];
            int vrow = kk + (lane & 7) + ((lane >> 3) & 1) * 8;
#pragma unroll
            for (int j = 0; j < 8; j++) {
                unsigned b0, b1;
                unsigned saddr = (unsigned)__cvta_generic_to_shared(&vbuf[vrow * 72 + j * 8]);
                asm volatile("ldmatrix.sync.aligned.m8n8.x2.trans.shared.b16 {%0,%1}, [%2];"
                             : "=r"(b0), "=r"(b1) : "r"(saddr));
                mma_f16(O[j], a0, a1, a2, a3, b0, b1);
            }
        }
        buf ^= 1;
    }

    float inv0 = 1.f / l0, inv1 = 1.f / l1;
    __half* og = ctx + ((size_t)(b * NQ + q0)) * Dd + h * DH;
#pragma unroll
    for (int j = 0; j < 8; j++) {
        int col = j * 8 + 2 * tg;
        __half2 h0 = __floats2half2_rn(O[j][0] * inv0, O[j][1] * inv0);
        __half2 h1 = __floats2half2_rn(O[j][2] * inv1, O[j][3] * inv1);
        *(unsigned*)&og[(size_t)(mw + g) * Dd + col] = h2u(h0);
        *(unsigned*)&og[(size_t)(mw + g + 8) * Dd + col] = h2u(h1);
    }
}

// ---------------- launch ------------------------------------------------------
extern "C" void kernel_launch(void* const* d_in, const int* in_sizes, int n_in,
                              void* d_out, int out_size) {
    const float* upd_in = (const float*)d_in[0];
    const float* emb    = (const float*)d_in[1];
    const float* mask   = (const float*)d_in[2];
    const float* Wq     = (const float*)d_in[3];
    const float* Wk     = (const float*)d_in[4];
    const float* Wv     = (const float*)d_in[5];
    const float* Wo     = (const float*)d_in[6];
    const float* W1     = (const float*)d_in[7];
    const float* b1     = (const float*)d_in[8];
    const float* W2     = (const float*)d_in[9];
    const float* b2     = (const float*)d_in[10];
    const float* sys_s  = (const float*)d_in[11];
    const float* sys_b  = (const float*)d_in[12];
    const float* eff_s  = (const float*)d_in[13];
    const float* eff_b  = (const float*)d_in[14];
    const float* in_s   = (const float*)d_in[15];
    const float* in_b   = (const float*)d_in[16];
    const float* out_s  = (const float*)d_in[17];
    const float* out_b  = (const float*)d_in[18];
    const int*   qidx   = (const int*)d_in[19];
    const int*   kidx   = (const int*)d_in[20];
    float* out = (float*)d_out;

    float *upd, *hb, *t1f, *t2;
    __half *qh, *kh, *Qh, *Kh, *Vh, *ctxh, *hh, *t1h, *WT;
    unsigned long long* mpk;
    cudaGetSymbolAddress((void**)&upd,  g_upd);
    cudaGetSymbolAddress((void**)&hb,   g_hb);
    cudaGetSymbolAddress((void**)&t1f,  g_t1f);
    cudaGetSymbolAddress((void**)&t2,   g_t2);
    cudaGetSymbolAddress((void**)&qh,   g_qh);
    cudaGetSymbolAddress((void**)&kh,   g_kh);
    cudaGetSymbolAddress((void**)&Qh,   g_Qh);
    cudaGetSymbolAddress((void**)&Kh,   g_Kh);
    cudaGetSymbolAddress((void**)&Vh,   g_Vh);
    cudaGetSymbolAddress((void**)&ctxh, g_ctxh);
    cudaGetSymbolAddress((void**)&hh,   g_hh);
    cudaGetSymbolAddress((void**)&t1h,  g_t1h);
    cudaGetSymbolAddress((void**)&WT,   g_WT);
    cudaGetSymbolAddress((void**)&mpk,  g_mpk);

    cudaFuncSetAttribute(flash_attn, cudaFuncAttributeMaxDynamicSharedMemorySize, 55296);
    cudaFuncSetAttribute(proj_qkv, cudaFuncAttributeMaxDynamicSharedMemorySize, 55296);
    cudaFuncSetAttribute(proj_h<0, 1>, cudaFuncAttributeMaxDynamicSharedMemorySize, 55296);
    cudaFuncSetAttribute(proj_h<0, 0>, cudaFuncAttributeMaxDynamicSharedMemorySize, 55296);
    cudaFuncSetAttribute(proj_h<1, 1>, cudaFuncAttributeMaxDynamicSharedMemorySize, 55296);

    int n_upd = Bb * NS * Dd;
    k_init<<<8192, 256>>>(upd_in, upd, n_upd);
    k_prep<<<dim3(8, 8, 6), dim3(32, 8)>>>(Wq, Wk, Wv, Wo, W1, W2, WT);
    k_maskpack<<<(Ll * NQ * 16 + 255) / 256, 256>>>(mask, mpk);

    const int DD2 = Dd * Dd;
    for (int l = 0; l < Ll; l++) {
        const unsigned long long* mpk_l = mpk + (size_t)l * NQ * 16;
        const int* qi = qidx + l * NQ;
        const int* ki = kidx + l * NK;

        k_gather_ln2<<<(Bb * NQ + Bb * NK) / 4, 256>>>(emb, upd, qi, ki,
                                                       sys_s, sys_b, qh, kh);

        proj_qkv<<<dim3(256, 4, 3), 256, 55296>>>(qh, kh, WT, Qh, Kh, Vh);

        flash_attn<<<dim3(NQ / 128, 1, Bb * Hh), 256, 55296>>>(Qh, Kh, Vh, mpk_l, ctxh);

        proj_h<0, 0><<<dim3(128, 4), 256, 55296>>>(ctxh, WT + 3 * DD2, nullptr, nullptr, t1f);
        k_ln<<<Bb * NQ / 4, 256>>>(t1f, in_s, in_b, hb, hh);

        proj_h<1, 1><<<dim3(128, 4), 256, 55296>>>(hh, WT + 4 * DD2, b1, t1h, nullptr);
        proj_h<0, 0><<<dim3(128, 4), 256, 55296>>>(t1h, WT + 5 * DD2, b2, nullptr, t2);

        k_dln_scatter<<<Bb * NQ / 4, 256>>>(hb, t2, out_s, out_b, eff_s, eff_b, qi, upd);
    }
    k_final<<<8192, 256>>>(upd, upd_in, out, n_upd);
}